// round 6
// baseline (speedup 1.0000x reference)
#include <cuda_runtime.h>
#include <cooperative_groups.h>
namespace cg = cooperative_groups;

#define BB 8
#define HH 256
#define WW 256
#define NPIX (BB*HH*WW)
#define N_ITERS 200
#define NCTAS 128          // 8 images * (4x4) 64x64 tiles -> 1 CTA per SM
#define NTHREADS 512       // 64 x 8 threads, 8 px per thread

// Double-buffered ubar halo exchange (alloc-free scratch)
__device__ float g_halo[2][NPIX];

__device__ __forceinline__ float clipf(float v, float b) {
    return fminf(fmaxf(v, -b), b);
}
__device__ __forceinline__ float ldcg(const float* p) {
    float v;
    asm volatile("ld.global.cg.f32 %0, [%1];" : "=f"(v) : "l"(p) : "memory");
    return v;
}

__global__ __launch_bounds__(NTHREADS, 1)
void tv_persist(const float* __restrict__ f,
                const float* __restrict__ lam,
                float* __restrict__ out)
{
    cg::grid_group grid = cg::this_grid();

    const float SIG  = 0.35355339f;
    const float TAUc = 0.35355339f;
    const float INV  = 1.0f / (1.0f + TAUc);

    // Double-buffered interior ubar tile (64 rows x 64 cols, +1 col pad)
    __shared__ float ubs[2][64][65];

    const int c   = blockIdx.x;
    const int img = c >> 4;
    const int t   = c & 15;
    const int j0  = (t & 3) * 64;
    const int i0  = (t >> 2) * 64;
    const int tx  = threadIdx.x & 63;
    const int ty  = threadIdx.x >> 6;     // 0..7
    const int j    = j0 + tx;
    const int itop = i0 + ty * 8;
    const int base = (img * HH + itop) * WW + j;   // pixel k at base + k*WW
    const int r0   = ty * 8;

    const bool has_up = (i0 > 0);
    const bool has_dn = (i0 + 64 < HH);
    const bool has_lf = (j0 > 0);
    const bool has_rt = (j0 + 64 < WW);

    // ---- Load all state into registers ----
    float u[8], ub[8], pc[8], qc[8], ql[8];
    float fv[8], lamx[8], lamy[8], lams[8];
#pragma unroll
    for (int k = 0; k < 8; k++) {
        const int i   = itop + k;
        const int idx = base + k * WW;
        float fk = f[idx];
        u[k] = ub[k] = fv[k] = fk;
        pc[k] = qc[k] = ql[k] = 0.f;
        lamx[k] = (i < HH - 1) ? lam[idx + WW] : 0.f;   // bound for p(i,j)
        lamy[k] = (j < WW - 1) ? lam[idx + 1]  : 0.f;   // bound for q(i,j)
        lams[k] = (j > 0)      ? lam[idx]      : 0.f;   // bound for q(i,j-1)
    }
    float pu_top = 0.f;                                  // p(itop-1, j) state
    const float pu_lam = (itop > 0) ? lam[base] : 0.f;

    for (int it = 0; it < N_ITERS; it++) {
        const int s = it & 1;

        // ---- stage interior ubar into SMEM (parity buffer) ----
#pragma unroll
        for (int k = 0; k < 8; k++) ubs[s][r0 + k][tx] = ub[k];

        // ---- publish tile-boundary ubar to the global halo ----
        float* H = g_halo[s];
        if (ty == 0) H[base] = ub[0];
        if (ty == 7) H[base + 7 * WW] = ub[7];
        if (tx == 0 || tx == 63) {
#pragma unroll
            for (int k = 0; k < 8; k++) H[base + k * WW] = ub[k];
        }

        grid.sync();   // global + block barrier; orders SMEM and L2 halo

        const float* Hc = g_halo[s];

        // ---- cross-strip vertical neighbors ----
        float ub_above = (ty > 0) ? ubs[s][r0 - 1][tx]
                        : (has_up ? ldcg(&Hc[base - WW]) : 0.f);
        float ub_below = (ty < 7) ? ubs[s][r0 + 8][tx]
                        : (has_dn ? ldcg(&Hc[base + 8 * WW]) : 0.f);

        // ---- one Chambolle-Pock iteration in registers ----
        pu_top = clipf(pu_top + SIG * (ub[0] - ub_above), pu_lam);
        float pu = pu_top;
#pragma unroll
        for (int k = 0; k < 8; k++) {
            float ub_b = (k < 7) ? ub[k + 1] : ub_below;
            float ub_l = (tx > 0)  ? ubs[s][r0 + k][tx - 1]
                       : (has_lf ? ldcg(&Hc[base + k * WW - 1]) : 0.f);
            float ub_r = (tx < 63) ? ubs[s][r0 + k][tx + 1]
                       : (has_rt ? ldcg(&Hc[base + k * WW + 1]) : 0.f);

            pc[k] = clipf(pc[k] + SIG * (ub_b - ub[k]), lamx[k]);
            qc[k] = clipf(qc[k] + SIG * (ub_r - ub[k]), lamy[k]);
            ql[k] = clipf(ql[k] + SIG * (ub[k] - ub_l), lams[k]);

            float div = (pu - pc[k]) + (ql[k] - qc[k]);
            float un  = (u[k] + TAUc * (fv[k] - div)) * INV;
            ub[k] = 2.f * un - u[k];
            u[k]  = un;
            pu    = pc[k];
        }
        // No __syncthreads: double buffer + the grid.sync one iteration ahead
        // separates iter-t reads of ubs[s]/g_halo[s] from iter-(t+2) writes.
    }

#pragma unroll
    for (int k = 0; k < 8; k++) out[base + k * WW] = u[k];
}

extern "C" void kernel_launch(void* const* d_in, const int* in_sizes, int n_in,
                              void* d_out, int out_size) {
    const float* f   = (const float*)d_in[0];
    const float* lam = (const float*)d_in[1];
    float* out = (float*)d_out;

    void* args[] = { (void*)&f, (void*)&lam, (void*)&out };
    cudaLaunchCooperativeKernel((void*)tv_persist,
                                dim3(NCTAS), dim3(NTHREADS),
                                args, 0, 0);
}

// round 7
// speedup vs baseline: 1.1056x; 1.1056x over previous
#include <cuda_runtime.h>
#include <cooperative_groups.h>
#include <cstdint>

#define BB 8
#define HH 256
#define WW 256
#define NPIX (BB*HH*WW)
#define N_ITERS 200
#define TILE_W 64
#define TILE_H 32
#define VPT 8
#define NCTAS 256          // 8 images * (4x8) 64x32 tiles, 2 CTAs/SM
#define NTHREADS 256       // 64 x 4 threads, 8 px/thread

// Double-buffered ubar halo exchange (alloc-free scratch)
__device__ float g_halo[2][NPIX];
// Monotone grid-barrier counter (zero-initialized once at module load)
__device__ unsigned long long g_count;

__device__ __forceinline__ float clipf(float v, float b) {
    return fminf(fmaxf(v, -b), b);
}
__device__ __forceinline__ float ldcg(const float* p) {
    float v;
    asm volatile("ld.global.cg.f32 %0, [%1];" : "=f"(v) : "l"(p) : "memory");
    return v;
}
__device__ __forceinline__ unsigned long long ld_acq_u64(const unsigned long long* p) {
    unsigned long long v;
    asm volatile("ld.acquire.gpu.global.u64 %0, [%1];" : "=l"(v) : "l"(p) : "memory");
    return v;
}
__device__ __forceinline__ void red_release_add1(unsigned long long* p) {
    unsigned long long one = 1ULL;
    asm volatile("red.release.gpu.global.add.u64 [%0], %1;" :: "l"(p), "l"(one) : "memory");
}

__global__ __launch_bounds__(NTHREADS, 2)
void tv_persist(const float* __restrict__ f,
                const float* __restrict__ lam,
                float* __restrict__ out)
{
    const float SIG  = 0.35355339f;
    const float TAUc = 0.35355339f;
    const float INV  = 1.0f / (1.0f + TAUc);
    const unsigned long long K = (unsigned long long)NCTAS * N_ITERS;

    // Double-buffered interior ubar tile
    __shared__ float ubs[2][TILE_H][TILE_W + 1];
    __shared__ unsigned long long sh_epoch;

    const int c  = blockIdx.x;
    const int b  = c >> 5;
    const int t  = c & 31;
    const int j0 = (t & 3) * TILE_W;
    const int i0 = (t >> 2) * TILE_H;
    const int tx = threadIdx.x & 63;
    const int ty = threadIdx.x >> 6;     // 0..3
    const int j    = j0 + tx;
    const int itop = i0 + ty * VPT;
    const int base = (b * HH + itop) * WW + j;   // pixel k at base + k*WW
    const int r0   = ty * VPT;

    const bool has_up = (i0 > 0);
    const bool has_dn = (i0 + TILE_H < HH);
    const bool has_lf = (j0 > 0);
    const bool has_rt = (j0 + TILE_W < WW);

    // Epoch recovery: counter grows by exactly K per launch; intra-launch
    // drift at entry is < NCTAS << K, so floor-to-K is race-proof.
    if (threadIdx.x == 0) {
        unsigned long long c0 = *(volatile unsigned long long*)&g_count;
        sh_epoch = (c0 / K) * K;
    }

    // ---- Load all state into registers ----
    float u[VPT], ub[VPT], pc[VPT], qc[VPT], ql[VPT];
    float fv[VPT], lamx[VPT], lamy[VPT], lams[VPT];
#pragma unroll
    for (int k = 0; k < VPT; k++) {
        const int i   = itop + k;
        const int idx = base + k * WW;
        float fk = f[idx];
        u[k] = ub[k] = fv[k] = fk;
        pc[k] = qc[k] = ql[k] = 0.f;
        lamx[k] = (i < HH - 1) ? lam[idx + WW] : 0.f;   // bound for p(i,j)
        lamy[k] = (j < WW - 1) ? lam[idx + 1]  : 0.f;   // bound for q(i,j)
        lams[k] = (j > 0)      ? lam[idx]      : 0.f;   // bound for q(i,j-1)
    }
    float pu_top = 0.f;                                  // p(itop-1, j)
    const float pu_lam = (itop > 0) ? lam[base] : 0.f;

    __syncthreads();   // sh_epoch visible
    const unsigned long long epoch = sh_epoch;

    for (int it = 0; it < N_ITERS; it++) {
        const int s = it & 1;

        // ---- stage interior ubar into SMEM (parity buffer) ----
#pragma unroll
        for (int k = 0; k < VPT; k++) ubs[s][r0 + k][tx] = ub[k];

        // ---- publish tile-boundary ubar to global halo ----
        float* H = g_halo[s];
        if (ty == 0) H[base] = ub[0];
        if (ty == 3) H[base + (VPT - 1) * WW] = ub[VPT - 1];
        if (tx == 0 || tx == 63) {
#pragma unroll
            for (int k = 0; k < VPT; k++) H[base + k * WW] = ub[k];
        }

        __syncthreads();   // SYNC1: all publishes + SMEM staging done

        // ---- lean split grid barrier: arrive ASAP, tight spin ----
        const unsigned long long target = epoch + (unsigned long long)(it + 1) * NCTAS;
        if (threadIdx.x == 0) {
            red_release_add1(&g_count);
            while ((long long)(ld_acq_u64(&g_count) - target) < 0) { }
        }
        __syncthreads();   // SYNC2: release observed; halo reads ordered

        const float* Hc = g_halo[s];

        // ---- cross-strip / cross-tile vertical neighbors ----
        float ub_above = (ty > 0) ? ubs[s][r0 - 1][tx]
                        : (has_up ? ldcg(&Hc[base - WW]) : 0.f);
        float ub_below = (ty < 3) ? ubs[s][r0 + VPT][tx]
                        : (has_dn ? ldcg(&Hc[base + VPT * WW]) : 0.f);

        // ---- one Chambolle-Pock iteration in registers ----
        pu_top = clipf(pu_top + SIG * (ub[0] - ub_above), pu_lam);
        float pu = pu_top;
#pragma unroll
        for (int k = 0; k < VPT; k++) {
            float ub_b = (k < VPT - 1) ? ub[k + 1] : ub_below;
            float ub_l = (tx > 0)  ? ubs[s][r0 + k][tx - 1]
                       : (has_lf ? ldcg(&Hc[base + k * WW - 1]) : 0.f);
            float ub_r = (tx < 63) ? ubs[s][r0 + k][tx + 1]
                       : (has_rt ? ldcg(&Hc[base + k * WW + 1]) : 0.f);

            pc[k] = clipf(pc[k] + SIG * (ub_b - ub[k]), lamx[k]);
            qc[k] = clipf(qc[k] + SIG * (ub_r - ub[k]), lamy[k]);
            ql[k] = clipf(ql[k] + SIG * (ub[k] - ub_l), lams[k]);

            float div = (pu - pc[k]) + (ql[k] - qc[k]);
            float un  = (u[k] + TAUc * (fv[k] - div)) * INV;
            ub[k] = 2.f * un - u[k];
            u[k]  = un;
            pu    = pc[k];
        }
        // Double buffers + SYNC1/SYNC2 of later iterations cover all WARs:
        // ubs[s]/g_halo[s] are rewritten at it+2, after every thread passed
        // the it+1 barriers, which happen after all it-reads completed.
    }

#pragma unroll
    for (int k = 0; k < VPT; k++) out[base + k * WW] = u[k];
}

extern "C" void kernel_launch(void* const* d_in, const int* in_sizes, int n_in,
                              void* d_out, int out_size) {
    const float* f   = (const float*)d_in[0];
    const float* lam = (const float*)d_in[1];
    float* out = (float*)d_out;

    // Cooperative launch only for the co-residency guarantee the hand-rolled
    // barrier requires; grid.sync() itself is not used.
    void* args[] = { (void*)&f, (void*)&lam, (void*)&out };
    cudaLaunchCooperativeKernel((void*)tv_persist,
                                dim3(NCTAS), dim3(NTHREADS),
                                args, 0, 0);
}

// round 8
// speedup vs baseline: 1.4815x; 1.3401x over previous
#include <cuda_runtime.h>
#include <cooperative_groups.h>
#include <cstdint>

#define BB 8
#define HH 256
#define WW 256
#define NPIX (BB*HH*WW)
#define N_ITERS 200
#define TILE_W 64
#define TILE_H 32
#define VPT 8
#define NCTAS 256          // 8 images * (4x8) tiles, 2 CTAs/SM
#define NTHREADS 256

// Double-buffered ubar halo exchange (alloc-free scratch)
__device__ float g_halo[2][NPIX];
// Split barrier: atomic arrive counter (leader-polled only) and release word
// (leader-written, everyone spins) on separate cache lines.
__device__ __align__(128) unsigned long long g_arrive;
__device__ __align__(128) unsigned long long g_release;

__device__ __forceinline__ float clipf(float v, float b) {
    return fminf(fmaxf(v, -b), b);
}
__device__ __forceinline__ unsigned long long ld_acq_u64(const unsigned long long* p) {
    unsigned long long v;
    asm volatile("ld.acquire.gpu.global.u64 %0, [%1];" : "=l"(v) : "l"(p) : "memory");
    return v;
}
__device__ __forceinline__ void st_rel_u64(unsigned long long* p, unsigned long long v) {
    asm volatile("st.release.gpu.global.u64 [%0], %1;" :: "l"(p), "l"(v) : "memory");
}
__device__ __forceinline__ void red_rel_add1(unsigned long long* p) {
    asm volatile("red.release.gpu.global.add.u64 [%0], %1;" :: "l"(p), "l"(1ULL) : "memory");
}

__global__ __launch_bounds__(NTHREADS, 2)
void tv_persist(const float* __restrict__ f,
                const float* __restrict__ lam,
                float* __restrict__ out)
{
    const float SIG  = 0.35355339f;
    const float TAUc = 0.35355339f;
    const float INV  = 1.0f / (1.0f + TAUc);
    const unsigned long long K = (unsigned long long)NCTAS * N_ITERS;

    __shared__ float ubs[TILE_H + 2][TILE_W + 2];

    const int c  = blockIdx.x;
    const int b  = c >> 5;
    const int t  = c & 31;
    const int j0 = (t & 3) * TILE_W;
    const int i0 = (t >> 2) * TILE_H;
    const int tx = threadIdx.x & 63;
    const int ty = threadIdx.x >> 6;     // 0..3
    const int j    = j0 + tx;
    const int itop = i0 + ty * VPT;
    const int base = (b * HH + itop) * WW + j;
    const int srow = 1 + ty * VPT;

    // Thread-0-private barrier epochs (replay-safe monotone counters).
    unsigned long long epoch_a = 0, epoch_r = 0;
    if (threadIdx.x == 0) {
        epoch_r = *(volatile unsigned long long*)&g_release;   // exact at entry
        if (c == 0) {
            unsigned long long a0 = *(volatile unsigned long long*)&g_arrive;
            epoch_a = (a0 / K) * K;                            // drift < NCTAS << K
        }
    }

    // ---- Load all state into registers ----
    float u[VPT], ub[VPT], pc[VPT], qc[VPT], ql[VPT];
    float fv[VPT], lamx[VPT], lamy[VPT], lams[VPT];
#pragma unroll
    for (int k = 0; k < VPT; k++) {
        const int i   = itop + k;
        const int idx = base + k * WW;
        float fk = f[idx];
        u[k] = ub[k] = fv[k] = fk;
        pc[k] = qc[k] = ql[k] = 0.f;
        lamx[k] = (i < HH - 1) ? lam[idx + WW] : 0.f;   // bound for p(i,j)
        lamy[k] = (j < WW - 1) ? lam[idx + 1]  : 0.f;   // bound for q(i,j)
        lams[k] = (j > 0)      ? lam[idx]      : 0.f;   // bound for q(i,j-1)
    }
    float pu_top = 0.f;                                  // p(itop-1, j)
    const float pu_lam = (itop > 0) ? lam[base] : 0.f;

    for (int it = 0; it < N_ITERS; it++) {
        float* H = g_halo[it & 1];

        // ---- stage interior ubar into SMEM ----
#pragma unroll
        for (int k = 0; k < VPT; k++) ubs[srow + k][1 + tx] = ub[k];

        // ---- publish tile-boundary ubar to global halo ----
        if (ty == 0) H[base] = ub[0];
        if (ty == 3) H[base + (VPT - 1) * WW] = ub[VPT - 1];
        if (tx == 0 || tx == 63) {
#pragma unroll
            for (int k = 0; k < VPT; k++) H[base + k * WW] = ub[k];
        }

        __syncthreads();   // publishes + SMEM staging complete

        // ---- split grid barrier (arrive line != spin line) ----
        if (threadIdx.x == 0) {
            red_rel_add1(&g_arrive);                       // orders prior stores
            const unsigned long long rtar = epoch_r + (unsigned long long)(it + 1);
            if (c == 0) {
                const unsigned long long atar =
                    epoch_a + (unsigned long long)(it + 1) * NCTAS;
                while ((long long)(ld_acq_u64(&g_arrive) - atar) < 0) { }
                st_rel_u64(&g_release, rtar);
            }
            while ((long long)(ld_acq_u64(&g_release) - rtar) < 0) { }
        }
        __syncthreads();   // release observed by all threads

        const float* Hc = g_halo[it & 1];

        // ---- pull neighbor halos into SMEM ring ----
        if (ty == 0)
            ubs[0][1 + tx]          = (i0 > 0)             ? Hc[base - WW]       : 0.f;
        if (ty == 3)
            ubs[TILE_H + 1][1 + tx] = (i0 + TILE_H < HH)   ? Hc[base + VPT * WW] : 0.f;
        if (tx == 0) {
#pragma unroll
            for (int k = 0; k < VPT; k++)
                ubs[srow + k][0]          = (j0 > 0)           ? Hc[base + k * WW - 1] : 0.f;
        }
        if (tx == 63) {
#pragma unroll
            for (int k = 0; k < VPT; k++)
                ubs[srow + k][TILE_W + 1] = (j0 + TILE_W < WW) ? Hc[base + k * WW + 1] : 0.f;
        }
        __syncthreads();

        // ---- one Chambolle-Pock iteration in registers ----
        float ub_above = ubs[srow - 1][1 + tx];
        pu_top = clipf(pu_top + SIG * (ub[0] - ub_above), pu_lam);
        float pu = pu_top;
#pragma unroll
        for (int k = 0; k < VPT; k++) {
            float ub_b = (k < VPT - 1) ? ub[k + 1] : ubs[srow + VPT][1 + tx];
            float ub_l = ubs[srow + k][tx];
            float ub_r = ubs[srow + k][2 + tx];

            pc[k] = clipf(pc[k] + SIG * (ub_b - ub[k]), lamx[k]);
            qc[k] = clipf(qc[k] + SIG * (ub_r - ub[k]), lamy[k]);
            ql[k] = clipf(ql[k] + SIG * (ub[k] - ub_l), lams[k]);

            float div = (pu - pc[k]) + (ql[k] - qc[k]);
            float un  = (u[k] + TAUc * (fv[k] - div)) * INV;
            ub[k] = 2.f * un - u[k];
            u[k]  = un;
            pu    = pc[k];
        }
        __syncthreads();   // SMEM WAR before next iteration's staging
    }

#pragma unroll
    for (int k = 0; k < VPT; k++) out[base + k * WW] = u[k];
}

extern "C" void kernel_launch(void* const* d_in, const int* in_sizes, int n_in,
                              void* d_out, int out_size) {
    const float* f   = (const float*)d_in[0];
    const float* lam = (const float*)d_in[1];
    float* out = (float*)d_out;

    // Cooperative launch for the co-residency guarantee the hand-rolled
    // barrier requires; grid.sync() itself is not used.
    void* args[] = { (void*)&f, (void*)&lam, (void*)&out };
    cudaLaunchCooperativeKernel((void*)tv_persist,
                                dim3(NCTAS), dim3(NTHREADS),
                                args, 0, 0);
}

// round 9
// speedup vs baseline: 3.2772x; 2.2120x over previous
#include <cuda_runtime.h>
#include <cooperative_groups.h>
namespace cg = cooperative_groups;

#define BB 8
#define HH 256
#define WW 256
#define NPIX (BB*HH*WW)
#define N_ITERS 200
#define TT 4                 // sub-iterations per exchange (halo width)
#define NB (N_ITERS/TT)      // 50 blocks
#define NCTAS 256            // 8 images * (4x8) 32x64 tiles, 2 CTAs/SM
#define NTHREADS 288         // 72 ext-cols * 4 row-groups, 10 rows each

// Double-buffered full-state exchange arrays (alloc-free scratch, 16MB)
__device__ float gU [2][NPIX];
__device__ float gUB[2][NPIX];
__device__ float gP [2][NPIX];
__device__ float gQ [2][NPIX];

__device__ __forceinline__ float clipf(float v, float b) {
    return fminf(fmaxf(v, -b), b);
}
__device__ __forceinline__ float ldcg(const float* p) {
    float v;
    asm volatile("ld.global.cg.f32 %0, [%1];" : "=f"(v) : "l"(p) : "memory");
    return v;
}

__global__ __launch_bounds__(NTHREADS, 2)
void tv_block(const float* __restrict__ f,
              const float* __restrict__ lam,
              float* __restrict__ out)
{
    cg::grid_group grid = cg::this_grid();

    const float SIG  = 0.35355339f;
    const float TAUc = 0.35355339f;
    const float INV  = 1.0f / (1.0f + TAUc);

    // Extended region: 40 rows x 72 cols (tile 32x64 + 4-ring), +1 pad ring.
    // Cell (r,c) -> smem [r+1][c+1]. Pads stay 0 (finite garbage for ring math).
    __shared__ float ubS[42][74];   // ubar: read by row/col neighbors
    __shared__ float qS [42][74];   // q: read by right-neighbor column
    __shared__ float pS [5][74];    // p of row-group boundary rows (9,19,29,39)

    const int cta = blockIdx.x;
    const int img = cta >> 5;
    const int t   = cta & 31;
    const int i0  = (t >> 2) * 32;
    const int j0  = (t & 3) * 64;
    const int tid = threadIdx.x;
    const int c   = tid % 72;        // ext col 0..71
    const int r4  = tid / 72;        // row group 0..3
    const int rb  = r4 * 10;         // first ext row of my strip

    const int gj     = j0 - TT + c;
    const bool col_in = (gj >= 0 && gj < WW);
    const int  gi0    = i0 - TT + rb;                 // global row of k=0
    const int  base   = (img * HH + gi0) * WW + gj;   // cell k at base + k*WW

    // Zero all SMEM (pads included)
    for (int x = tid; x < 42 * 74; x += NTHREADS) ((float*)ubS)[x] = 0.f;
    for (int x = tid; x < 42 * 74; x += NTHREADS) ((float*)qS)[x]  = 0.f;
    for (int x = tid; x < 5 * 74;  x += NTHREADS) ((float*)pS)[x]  = 0.f;

    // ---- per-cell state in registers ----
    float u[10], ub[10], p[10], q[10], fv[10], lx[10], ly[10];
#pragma unroll
    for (int k = 0; k < 10; k++) {
        const int gi  = gi0 + k;
        const bool ii = col_in && (gi >= 0) && (gi < HH);
        const int idx = base + k * WW;
        const float fk = ii ? f[idx] : 0.f;
        fv[k] = fk; u[k] = fk; ub[k] = fk; p[k] = 0.f; q[k] = 0.f;
        lx[k] = (ii && gi < HH - 1) ? lam[idx + WW] : 0.f;  // bound for p(r,c)
        ly[k] = (ii && gj < WW - 1) ? lam[idx + 1]  : 0.f;  // bound for q(r,c)
    }
    __syncthreads();
#pragma unroll
    for (int k = 0; k < 10; k++) ubS[rb + k + 1][c + 1] = ub[k];
    __syncthreads();

#pragma unroll 1
    for (int blk = 0; blk < NB; blk++) {
        if (blk) {
            const int sb = blk & 1;
            // ---- publish interior frame (width-TT border of the true tile) ----
#pragma unroll
            for (int k = 0; k < 10; k++) {
                const int r = rb + k;
                const bool interior = (r >= 4 && r < 36 && c >= 4 && c < 68);
                if (interior && (r < 8 || r >= 32 || c < 8 || c >= 64)) {
                    const int idx = base + k * WW;
                    gU [sb][idx] = u[k];  gUB[sb][idx] = ub[k];
                    gP [sb][idx] = p[k];  gQ [sb][idx] = q[k];
                }
            }
            grid.sync();
            // ---- refresh ring (full state) from neighbors' publishes ----
#pragma unroll
            for (int k = 0; k < 10; k++) {
                const int r  = rb + k;
                const int gi = gi0 + k;
                const bool ring = (r < 4 || r >= 36 || c < 4 || c >= 68);
                if (ring && col_in && gi >= 0 && gi < HH) {
                    const int idx = base + k * WW;
                    u[k]  = ldcg(&gU [sb][idx]);
                    ub[k] = ldcg(&gUB[sb][idx]);
                    p[k]  = ldcg(&gP [sb][idx]);
                    q[k]  = ldcg(&gQ [sb][idx]);
                    ubS[r + 1][c + 1] = ub[k];
                }
            }
            __syncthreads();
        }

#pragma unroll 1
        for (int s = 0; s < TT; s++) {
            // ---- phase 1: dual update (p, q) over the whole ext region ----
            const float ub_below_last = ubS[rb + 11][c + 1];
#pragma unroll
            for (int k = 0; k < 10; k++) {
                const float ub_b = (k < 9) ? ub[k + 1] : ub_below_last;
                const float ub_r = ubS[rb + k + 1][c + 2];
                p[k] = clipf(p[k] + SIG * (ub_b - ub[k]), lx[k]);
                q[k] = clipf(q[k] + SIG * (ub_r - ub[k]), ly[k]);
                qS[rb + k + 1][c + 1] = q[k];
            }
            pS[r4 + 1][c + 1] = p[9];
            __syncthreads();

            // ---- phase 2: primal update (u, ubar) ----
            const float p_up = pS[r4][c + 1];   // p(rb-1, c)
#pragma unroll
            for (int k = 0; k < 10; k++) {
                const float pm  = (k > 0) ? p[k - 1] : p_up;
                const float qm  = qS[rb + k + 1][c];        // q(r, c-1)
                const float div = (pm - p[k]) + (qm - q[k]);
                const float un  = (u[k] + TAUc * (fv[k] - div)) * INV;
                ub[k] = 2.f * un - u[k];
                u[k]  = un;
                ubS[rb + k + 1][c + 1] = ub[k];
            }
            __syncthreads();
        }
    }

    // ---- write interior result ----
#pragma unroll
    for (int k = 0; k < 10; k++) {
        const int r = rb + k;
        if (r >= 4 && r < 36 && c >= 4 && c < 68)
            out[base + k * WW] = u[k];
    }
}

extern "C" void kernel_launch(void* const* d_in, const int* in_sizes, int n_in,
                              void* d_out, int out_size) {
    const float* f   = (const float*)d_in[0];
    const float* lam = (const float*)d_in[1];
    float* out = (float*)d_out;

    void* args[] = { (void*)&f, (void*)&lam, (void*)&out };
    cudaLaunchCooperativeKernel((void*)tv_block,
                                dim3(NCTAS), dim3(NTHREADS),
                                args, 0, 0);
}

// round 10
// speedup vs baseline: 3.4339x; 1.0478x over previous
#include <cuda_runtime.h>
#include <cooperative_groups.h>
namespace cg = cooperative_groups;

#define BB 8
#define HH 256
#define WW 256
#define NPIX (BB*HH*WW)
#define N_ITERS 200
#define TT 4                 // halo width / sub-iterations per exchange
#define NB (N_ITERS/TT)      // 50 exchange rounds
#define NCTAS 256            // 8 images * (4x8) 32x64 tiles, 2 CTAs/SM
#define NTHREADS 288         // 36 column-pairs x 8 row groups
#define RPT 5                // rows per thread (x2 cols = 10 cells)
#define EXT_H 40
#define EXT_W 72

// Double-buffered full-state exchange arrays (alloc-free scratch)
__device__ float gU [2][NPIX];
__device__ float gUB[2][NPIX];
__device__ float gP [2][NPIX];
__device__ float gQ [2][NPIX];

__device__ __forceinline__ float clipf(float v, float b) {
    return fminf(fmaxf(v, -b), b);
}
__device__ __forceinline__ float ldcg(const float* p) {
    float v;
    asm volatile("ld.global.cg.f32 %0, [%1];" : "=f"(v) : "l"(p) : "memory");
    return v;
}

__global__ __launch_bounds__(NTHREADS, 2)
void tv_block(const float* __restrict__ f,
              const float* __restrict__ lam,
              float* __restrict__ out)
{
    cg::grid_group grid = cg::this_grid();

    const float SIG  = 0.35355339f;
    const float TAUc = 0.35355339f;
    const float INV  = 1.0f / (1.0f + TAUc);

    // Compact cross-thread arrays (only what neighbors actually read):
    __shared__ float ubE[EXT_H][37];   // ub of even ext col 2cp at [r][cp]; pad cp=36 (=0)
    __shared__ float qO [EXT_H][38];   // q of odd ext col 2cp+1 at [r][cp+1]; pad [r][0]
    __shared__ float ubB[9][EXT_W];    // first-row ub of each row group; pad rg=8
    __shared__ float pB [9][EXT_W];    // last-row p of each group at [rg+1][c]; pad [0]

    const int cta = blockIdx.x;
    const int img = cta >> 5;
    const int t   = cta & 31;
    const int i0  = (t >> 2) * 32;
    const int j0  = (t & 3) * 64;
    const int tid = threadIdx.x;
    const int cp  = tid % 36;          // column pair 0..35
    const int rg  = tid / 36;          // row group 0..7
    const int rb  = rg * RPT;          // first ext row of my strip
    const int c0  = 2 * cp;            // my even ext col

    const int gi_top = i0 - TT + rb;
    const int gj0    = j0 - TT + c0;
    const int base   = (img * HH + gi_top) * WW + gj0;  // cell (k,e) at base+k*WW+e

    // Zero all SMEM (pads stay 0 = finite garbage for ring math)
    for (int x = tid; x < EXT_H * 37; x += NTHREADS) ((float*)ubE)[x] = 0.f;
    for (int x = tid; x < EXT_H * 38; x += NTHREADS) ((float*)qO )[x] = 0.f;
    for (int x = tid; x < 9 * EXT_W;  x += NTHREADS) ((float*)ubB)[x] = 0.f;
    for (int x = tid; x < 9 * EXT_W;  x += NTHREADS) ((float*)pB )[x] = 0.f;

    // ---- per-cell state in registers (n = 2k+e) ----
    float u[10], ub[10], p[10], q[10], fv[10], lx[10], ly[10];
#pragma unroll
    for (int k = 0; k < RPT; k++) {
#pragma unroll
        for (int e = 0; e < 2; e++) {
            const int n  = 2 * k + e;
            const int gi = gi_top + k, gj = gj0 + e;
            const bool ii = (gi >= 0 && gi < HH && gj >= 0 && gj < WW);
            const int idx = base + k * WW + e;
            const float fk = ii ? f[idx] : 0.f;
            fv[n] = fk; u[n] = fk; ub[n] = fk; p[n] = 0.f; q[n] = 0.f;
            lx[n] = (ii && gi < HH - 1) ? lam[idx + WW] : 0.f;  // bound for p(r,c)
            ly[n] = (ii && gj < WW - 1) ? lam[idx + 1]  : 0.f;  // bound for q(r,c)
        }
    }
    __syncthreads();   // zeros complete before targeted writes
#pragma unroll
    for (int k = 0; k < RPT; k++) ubE[rb + k][cp] = ub[2 * k];
    ubB[rg][c0] = ub[0]; ubB[rg][c0 + 1] = ub[1];
    __syncthreads();

#pragma unroll 1
    for (int blk = 0; blk < NB; blk++) {
        if (blk) {
            const int sb = blk & 1;
            // ---- publish interior frame (width-TT border of the true tile) ----
#pragma unroll
            for (int k = 0; k < RPT; k++) {
#pragma unroll
                for (int e = 0; e < 2; e++) {
                    const int n = 2 * k + e, r = rb + k, c = c0 + e;
                    const bool interior = (r >= TT && r < EXT_H - TT &&
                                           c >= TT && c < EXT_W - TT);
                    if (interior && (r < 2*TT || r >= EXT_H - 2*TT ||
                                     c < 2*TT || c >= EXT_W - 2*TT)) {
                        const int idx = base + k * WW + e;
                        gU [sb][idx] = u[n];  gUB[sb][idx] = ub[n];
                        gP [sb][idx] = p[n];  gQ [sb][idx] = q[n];
                    }
                }
            }
            grid.sync();
            // ---- refresh ring (full state) from neighbors' publishes ----
#pragma unroll
            for (int k = 0; k < RPT; k++) {
#pragma unroll
                for (int e = 0; e < 2; e++) {
                    const int n = 2 * k + e, r = rb + k, c = c0 + e;
                    const int gi = gi_top + k, gj = gj0 + e;
                    const bool ring = (r < TT || r >= EXT_H - TT ||
                                       c < TT || c >= EXT_W - TT);
                    if (ring && gi >= 0 && gi < HH && gj >= 0 && gj < WW) {
                        const int idx = base + k * WW + e;
                        u[n]  = ldcg(&gU [sb][idx]);
                        ub[n] = ldcg(&gUB[sb][idx]);
                        p[n]  = ldcg(&gP [sb][idx]);
                        q[n]  = ldcg(&gQ [sb][idx]);
                        if (e == 0) ubE[r][cp] = ub[n];
                        if (k == 0) ubB[rg][c] = ub[n];
                    }
                }
            }
            __syncthreads();
        }

#pragma unroll 1
        for (int s = 0; s < TT; s++) {
            // ---- phase 1: dual update (p, q) ----
            const float ubb0 = ubB[rg + 1][c0];
            const float ubb1 = ubB[rg + 1][c0 + 1];
#pragma unroll
            for (int k = 0; k < RPT; k++) {
                const int r = rb + k;
                {   // even column: ub_right is own register ub[n+1]
                    const int n = 2 * k;
                    const float ub_b = (k < RPT - 1) ? ub[n + 2] : ubb0;
                    p[n] = clipf(p[n] + SIG * (ub_b     - ub[n]), lx[n]);
                    q[n] = clipf(q[n] + SIG * (ub[n + 1] - ub[n]), ly[n]);
                }
                {   // odd column: ub_right from right thread's even col
                    const int n = 2 * k + 1;
                    const float ub_b = (k < RPT - 1) ? ub[n + 2] : ubb1;
                    const float ub_r = ubE[r][cp + 1];
                    p[n] = clipf(p[n] + SIG * (ub_b - ub[n]), lx[n]);
                    q[n] = clipf(q[n] + SIG * (ub_r - ub[n]), ly[n]);
                    qO[r][cp + 1] = q[n];
                }
            }
            pB[rg + 1][c0]     = p[2 * (RPT - 1)];
            pB[rg + 1][c0 + 1] = p[2 * (RPT - 1) + 1];
            __syncthreads();

            // ---- phase 2: primal update (u, ubar) ----
            float pu0 = pB[rg][c0];
            float pu1 = pB[rg][c0 + 1];
#pragma unroll
            for (int k = 0; k < RPT; k++) {
                const int r = rb + k;
                const float qw = qO[r][cp];   // q(r, c0-1) from left thread
                {   // even column
                    const int n = 2 * k;
                    const float div = (pu0 - p[n]) + (qw - q[n]);
                    const float un  = (u[n] + TAUc * (fv[n] - div)) * INV;
                    ub[n] = 2.f * un - u[n];  u[n] = un;  pu0 = p[n];
                    ubE[r][cp] = ub[n];
                }
                {   // odd column: q_left is own register q[n-1]
                    const int n = 2 * k + 1;
                    const float div = (pu1 - p[n]) + (q[n - 1] - q[n]);
                    const float un  = (u[n] + TAUc * (fv[n] - div)) * INV;
                    ub[n] = 2.f * un - u[n];  u[n] = un;  pu1 = p[n];
                }
            }
            ubB[rg][c0] = ub[0];  ubB[rg][c0 + 1] = ub[1];
            __syncthreads();
        }
    }

    // ---- write interior result ----
#pragma unroll
    for (int k = 0; k < RPT; k++) {
#pragma unroll
        for (int e = 0; e < 2; e++) {
            const int r = rb + k, c = c0 + e;
            if (r >= TT && r < EXT_H - TT && c >= TT && c < EXT_W - TT)
                out[base + k * WW + e] = u[2 * k + e];
        }
    }
}

extern "C" void kernel_launch(void* const* d_in, const int* in_sizes, int n_in,
                              void* d_out, int out_size) {
    const float* f   = (const float*)d_in[0];
    const float* lam = (const float*)d_in[1];
    float* out = (float*)d_out;

    void* args[] = { (void*)&f, (void*)&lam, (void*)&out };
    cudaLaunchCooperativeKernel((void*)tv_block,
                                dim3(NCTAS), dim3(NTHREADS),
                                args, 0, 0);
}